// round 2
// baseline (speedup 1.0000x reference)
#include <cuda_runtime.h>
#include <math_constants.h>

// labels[c] = argmax_q code_book[c][q]
//   == reference argmin_q (tn[b,l,c] - cbn[c,q]) since tn is constant over q
//   and cbn is a monotone-increasing affine map of code_book.
// Stored as float (output dtype hypothesis: float32).
__device__ __align__(16) float g_labels_f[256];

static constexpr int C    = 256;
static constexpr int Qdim = 256;

// One warp per codebook row. Strict-greater update + min-index tie-break
// reproduces jnp.argmin first-occurrence semantics under the monotone map.
__global__ void row_argmax_kernel(const float* __restrict__ code_book) {
    const int c    = blockIdx.x;
    const int lane = threadIdx.x;
    const float* __restrict__ row = code_book + c * Qdim;

    float bv = -CUDART_INF_F;
    int   bi = 0;
#pragma unroll
    for (int k = 0; k < Qdim / 32; ++k) {
        const int   q = k * 32 + lane;
        const float v = __ldg(row + q);
        if (v > bv) { bv = v; bi = q; }   // strict > keeps earliest q per lane
    }
#pragma unroll
    for (int off = 16; off; off >>= 1) {
        const float ov = __shfl_down_sync(0xffffffffu, bv, off);
        const int   oi = __shfl_down_sync(0xffffffffu, bi, off);
        if (ov > bv || (ov == bv && oi < bi)) { bv = ov; bi = oi; }
    }
    if (lane == 0) g_labels_f[c] = (float)bi;
}

// Broadcast the 256-label row across all B*L = 2048 output rows.
// Output layout (B,L,C) row-major => pattern repeats every 256 floats = 64 float4.
__global__ void broadcast_labels_kernel(float4* __restrict__ out, int n4) {
    const int idx = blockIdx.x * blockDim.x + threadIdx.x;
    if (idx >= n4) return;
    const float4* __restrict__ lab4 = reinterpret_cast<const float4*>(g_labels_f);
    out[idx] = lab4[idx & (C / 4 - 1)];
}

extern "C" void kernel_launch(void* const* d_in, const int* in_sizes, int n_in,
                              void* d_out, int out_size) {
    // Locate code_book robustly by element count: sizes are
    // input_values=2097152, W=262144, code_book=65536, raw_signal=1 (all distinct).
    const float* code_book = nullptr;
    for (int i = 0; i < n_in; ++i) {
        if (in_sizes[i] == C * Qdim) { code_book = (const float*)d_in[i]; break; }
    }
    if (!code_book) code_book = (const float*)d_in[2];  // fallback: dict order

    row_argmax_kernel<<<C, 32>>>(code_book);

    const int n4 = out_size / 4;               // 524288 / 4 = 131072 float4
    const int threads = 256;
    const int blocks = (n4 + threads - 1) / threads;
    broadcast_labels_kernel<<<blocks, threads>>>(reinterpret_cast<float4*>(d_out), n4);
}